// round 6
// baseline (speedup 1.0000x reference)
#include <cuda_runtime.h>
#include <cuda_bf16.h>
#include <cuda_fp16.h>
#include <cstdint>

#define N_NODES 100000
#define N_EDGES 1600000
#define D_IN    256
#define D_OUT   128

#define SCAN_BLOCK 1024
#define N_SCAN_BLOCKS ((N_NODES + SCAN_BLOCK - 1) / SCAN_BLOCK)   // 98

typedef unsigned long long ull;

// Device scratch (static __device__ arrays only; no allocation anywhere).
__device__ __half g_supph[(size_t)N_NODES * D_OUT];    // 25.6 MB (fp16 support)
__device__ int   g_count[N_NODES];
__device__ int   g_offsets[N_NODES + 1];
__device__ int   g_cursor[N_NODES];
__device__ int   g_bsum[N_SCAN_BLOCKS];
__device__ int2  g_sw[N_EDGES];                        // packed (src, bits(w))

// ---------------------------------------------------------------------------
// helpers
// ---------------------------------------------------------------------------
__device__ __forceinline__ void cp_async16(void* smem_dst, const void* gmem_src) {
    uint32_t s = (uint32_t)__cvta_generic_to_shared(smem_dst);
    asm volatile("cp.async.ca.shared.global [%0], [%1], 16;" :: "r"(s), "l"(gmem_src));
}
__device__ __forceinline__ void cp_async_commit() {
    asm volatile("cp.async.commit_group;");
}
__device__ __forceinline__ void cp_async_wait_all() {
    asm volatile("cp.async.wait_group 0;");
}
// duplicate a float into both lanes of a 64-bit f32x2 register
__device__ __forceinline__ ull pack2(float v) {
    ull r;
    asm("mov.b64 %0, {%1, %1};" : "=l"(r) : "f"(v));
    return r;
}
// d = a * b + d  on packed f32x2 (Blackwell dual-fp32 pipe)
__device__ __forceinline__ void ffma2(ull& d, ull a, ull b) {
    asm("fma.rn.f32x2 %0, %1, %2, %0;" : "+l"(d) : "l"(a), "l"(b));
}

// ---------------------------------------------------------------------------
// GEMM: support = x @ W (fp32 math via f32x2, fp16 output).
// BM=128, BN=128, BK=8, 256 threads, 8x8 reg tile, rows paired for f32x2.
// Double-buffered smem, cp.async for W, register-staged x.
// ---------------------------------------------------------------------------
__global__ __launch_bounds__(256) void gemm_kernel(const float* __restrict__ x,
                                                   const float* __restrict__ W) {
    __shared__ float As[2][8][132];    // [buf][k][row], padded; k-row = 528B (16B mult)
    __shared__ float Bs[2][8][128];    // [buf][k][col]

    const int tid = threadIdx.x;
    const int block_row = blockIdx.x * 128;
    const int tx = tid & 15;        // 16 col groups of 8
    const int ty = tid >> 4;        // 16 row groups of 8

    const int lr = tid >> 1;             // A load: row 0..127
    const int lk = (tid & 1) * 4;        // A load: k offset 0 or 4
    const int bk = tid >> 5;             // B load: k-row 0..7
    const int bc = (tid & 31) * 4;       // B load: col

    // accp[rp][c] packs output rows (ty*8+2rp, ty*8+2rp+1) for column tx*8+c
    ull accp[4][8];
#pragma unroll
    for (int rp = 0; rp < 4; ++rp)
#pragma unroll
        for (int c = 0; c < 8; ++c) accp[rp][c] = 0ull;

    const int grow = block_row + lr;
    const bool arow_ok = (grow < N_NODES);
    const float* xrow = x + (size_t)grow * D_IN;

    // ---- prologue: tile 0 ----
    float4 av = arow_ok ? __ldg((const float4*)(xrow + lk))
                        : make_float4(0.f, 0.f, 0.f, 0.f);
    cp_async16(&Bs[0][bk][bc], W + (size_t)bk * D_OUT + bc);
    cp_async_commit();
    As[0][lk + 0][lr] = av.x;
    As[0][lk + 1][lr] = av.y;
    As[0][lk + 2][lr] = av.z;
    As[0][lk + 3][lr] = av.w;
    cp_async_wait_all();
    __syncthreads();

    int buf = 0;
#pragma unroll 1
    for (int k0 = 0; k0 < D_IN; k0 += 8) {
        const int nxt = buf ^ 1;
        const bool has_next = (k0 + 8) < D_IN;
        float4 av2;
        if (has_next) {
            av2 = arow_ok ? __ldg((const float4*)(xrow + k0 + 8 + lk))
                          : make_float4(0.f, 0.f, 0.f, 0.f);
            cp_async16(&Bs[nxt][bk][bc], W + (size_t)(k0 + 8 + bk) * D_OUT + bc);
            cp_async_commit();
        }

#pragma unroll
        for (int kk = 0; kk < 8; ++kk) {
            // a-pairs: 4x 64-bit lanes straight from shared (rows ty*8 .. ty*8+7)
            longlong2 ap01 = *(const longlong2*)&As[buf][kk][ty * 8];
            longlong2 ap23 = *(const longlong2*)&As[buf][kk][ty * 8 + 4];
            ull ap[4];
            ap[0] = (ull)ap01.x; ap[1] = (ull)ap01.y;
            ap[2] = (ull)ap23.x; ap[3] = (ull)ap23.y;
            // b: 8 scalars, each duplicated into an f32x2 register (ALU pipe)
            float4 b0 = *(const float4*)&Bs[buf][kk][tx * 8];
            float4 b1 = *(const float4*)&Bs[buf][kk][tx * 8 + 4];
            ull bd[8];
            bd[0] = pack2(b0.x); bd[1] = pack2(b0.y);
            bd[2] = pack2(b0.z); bd[3] = pack2(b0.w);
            bd[4] = pack2(b1.x); bd[5] = pack2(b1.y);
            bd[6] = pack2(b1.z); bd[7] = pack2(b1.w);
#pragma unroll
            for (int rp = 0; rp < 4; ++rp)
#pragma unroll
                for (int c = 0; c < 8; ++c)
                    ffma2(accp[rp][c], ap[rp], bd[c]);
        }

        if (has_next) {
            As[nxt][lk + 0][lr] = av2.x;
            As[nxt][lk + 1][lr] = av2.y;
            As[nxt][lk + 2][lr] = av2.z;
            As[nxt][lk + 3][lr] = av2.w;
            cp_async_wait_all();
            __syncthreads();
        }
        buf = nxt;
    }

    // epilogue: unpack row pairs, convert to fp16, 16B stores
    const int r0base = block_row + ty * 8;
#pragma unroll
    for (int rp = 0; rp < 4; ++rp) {
        const int r0 = r0base + 2 * rp;
        const int r1 = r0 + 1;
        __half2 h0[4], h1[4];
#pragma unroll
        for (int i = 0; i < 4; ++i) {
            float2 va = *(float2*)&accp[rp][2 * i];      // .x = row r0, .y = row r1
            float2 vb = *(float2*)&accp[rp][2 * i + 1];
            h0[i] = __floats2half2_rn(va.x, vb.x);
            h1[i] = __floats2half2_rn(va.y, vb.y);
        }
        if (r0 < N_NODES)
            *(uint4*)(g_supph + (size_t)r0 * D_OUT + tx * 8) = *(uint4*)h0;
        if (r1 < N_NODES)
            *(uint4*)(g_supph + (size_t)r1 * D_OUT + tx * 8) = *(uint4*)h1;
    }
}

// ---------------------------------------------------------------------------
// CSR-by-dst build
// ---------------------------------------------------------------------------
__global__ void zero_kernel() {
    int i = blockIdx.x * blockDim.x + threadIdx.x;
    if (i < N_NODES) g_count[i] = 0;
}

__global__ void hist_kernel(const int* __restrict__ edst) {
    int e4 = blockIdx.x * blockDim.x + threadIdx.x;
    if (e4 < N_EDGES / 4) {
        int4 d = ((const int4*)edst)[e4];
        atomicAdd(&g_count[d.x], 1);
        atomicAdd(&g_count[d.y], 1);
        atomicAdd(&g_count[d.z], 1);
        atomicAdd(&g_count[d.w], 1);
    }
}

__global__ __launch_bounds__(SCAN_BLOCK) void scan1_kernel() {
    __shared__ int warp_sums[32];
    const int t = threadIdx.x;
    const int idx = blockIdx.x * SCAN_BLOCK + t;
    const int lane = t & 31;
    const int wrp  = t >> 5;
    int v = (idx < N_NODES) ? g_count[idx] : 0;
    int incl = v;
#pragma unroll
    for (int off = 1; off < 32; off <<= 1) {
        int n = __shfl_up_sync(0xffffffffu, incl, off);
        if (lane >= off) incl += n;
    }
    if (lane == 31) warp_sums[wrp] = incl;
    __syncthreads();
    if (t < 32) {
        int s = warp_sums[t];
        int si = s;
#pragma unroll
        for (int off = 1; off < 32; off <<= 1) {
            int n = __shfl_up_sync(0xffffffffu, si, off);
            if (t >= off) si += n;
        }
        warp_sums[t] = si - s;   // exclusive warp prefix
    }
    __syncthreads();
    int excl = incl - v + warp_sums[wrp];
    if (idx < N_NODES) g_offsets[idx] = excl;
    if (t == SCAN_BLOCK - 1) g_bsum[blockIdx.x] = excl + v;
}

__global__ void scan2_kernel() {
    __shared__ int ws[4];
    const int t = threadIdx.x;          // 128 threads
    const int lane = t & 31, wrp = t >> 5;
    int v = (t < N_SCAN_BLOCKS) ? g_bsum[t] : 0;
    int incl = v;
#pragma unroll
    for (int off = 1; off < 32; off <<= 1) {
        int n = __shfl_up_sync(0xffffffffu, incl, off);
        if (lane >= off) incl += n;
    }
    if (lane == 31) ws[wrp] = incl;
    __syncthreads();
    int add = 0;
#pragma unroll
    for (int w = 0; w < 4; ++w) add += (w < wrp) ? ws[w] : 0;
    if (t < N_SCAN_BLOCKS) g_bsum[t] = incl - v + add;   // exclusive
}

__global__ void scan3_kernel() {
    int idx = blockIdx.x * blockDim.x + threadIdx.x;
    if (idx < N_NODES) {
        int off = g_offsets[idx] + g_bsum[idx / SCAN_BLOCK];
        g_offsets[idx] = off;
        g_cursor[idx]  = off;
    }
    if (idx == 0) g_offsets[N_NODES] = N_EDGES;
}

__global__ void place_kernel(const int* __restrict__ esrc,
                             const int* __restrict__ edst,
                             const float* __restrict__ ew) {
    int e = blockIdx.x * blockDim.x + threadIdx.x;
    if (e >= N_EDGES) return;
    int d = edst[e];
    int pos = atomicAdd(&g_cursor[d], 1);
    g_sw[pos] = make_int2(esrc[e], __float_as_int(ew[e]));
}

// ---------------------------------------------------------------------------
// Pull: warp per dst node, 4 fp16 gathers in flight (8B/lane), fp32 accumulate.
// out[n] = b + sum_e w_e * support[src_e]. No atomics.
// ---------------------------------------------------------------------------
__global__ __launch_bounds__(256) void pull_kernel(const float* __restrict__ b,
                                                   float* __restrict__ out) {
    const int n    = (blockIdx.x * blockDim.x + threadIdx.x) >> 5;
    const int lane = threadIdx.x & 31;
    if (n >= N_NODES) return;

    const int start = __ldg(&g_offsets[n]);
    const int end   = __ldg(&g_offsets[n + 1]);

    float4 acc0 = make_float4(0.f, 0.f, 0.f, 0.f);
    float4 acc1 = make_float4(0.f, 0.f, 0.f, 0.f);
    const ull* sup = (const ull*)g_supph;   // 4 halves per 8B
    const int loff = lane;                  // lane's 8B chunk within a 256B row

    int j = start;
    for (; j + 3 < end; j += 4) {
        int2 sw0 = __ldg(&g_sw[j]);
        int2 sw1 = __ldg(&g_sw[j + 1]);
        int2 sw2 = __ldg(&g_sw[j + 2]);
        int2 sw3 = __ldg(&g_sw[j + 3]);
        ull u0 = __ldg(sup + (size_t)sw0.x * (D_OUT / 4) + loff);
        ull u1 = __ldg(sup + (size_t)sw1.x * (D_OUT / 4) + loff);
        ull u2 = __ldg(sup + (size_t)sw2.x * (D_OUT / 4) + loff);
        ull u3 = __ldg(sup + (size_t)sw3.x * (D_OUT / 4) + loff);
        float w0 = __int_as_float(sw0.y), w1 = __int_as_float(sw1.y);
        float w2 = __int_as_float(sw2.y), w3 = __int_as_float(sw3.y);

        float2 a0 = __half22float2(((const __half2*)&u0)[0]);
        float2 b0v = __half22float2(((const __half2*)&u0)[1]);
        float2 a1 = __half22float2(((const __half2*)&u1)[0]);
        float2 b1v = __half22float2(((const __half2*)&u1)[1]);
        float2 a2 = __half22float2(((const __half2*)&u2)[0]);
        float2 b2v = __half22float2(((const __half2*)&u2)[1]);
        float2 a3 = __half22float2(((const __half2*)&u3)[0]);
        float2 b3v = __half22float2(((const __half2*)&u3)[1]);

        acc0.x = fmaf(w0, a0.x, acc0.x); acc0.y = fmaf(w0, a0.y, acc0.y);
        acc0.z = fmaf(w0, b0v.x, acc0.z); acc0.w = fmaf(w0, b0v.y, acc0.w);
        acc1.x = fmaf(w1, a1.x, acc1.x); acc1.y = fmaf(w1, a1.y, acc1.y);
        acc1.z = fmaf(w1, b1v.x, acc1.z); acc1.w = fmaf(w1, b1v.y, acc1.w);
        acc0.x = fmaf(w2, a2.x, acc0.x); acc0.y = fmaf(w2, a2.y, acc0.y);
        acc0.z = fmaf(w2, b2v.x, acc0.z); acc0.w = fmaf(w2, b2v.y, acc0.w);
        acc1.x = fmaf(w3, a3.x, acc1.x); acc1.y = fmaf(w3, a3.y, acc1.y);
        acc1.z = fmaf(w3, b3v.x, acc1.z); acc1.w = fmaf(w3, b3v.y, acc1.w);
    }
    for (; j < end; ++j) {
        int2 sw0 = __ldg(&g_sw[j]);
        float w0 = __int_as_float(sw0.y);
        ull u0 = __ldg(sup + (size_t)sw0.x * (D_OUT / 4) + loff);
        float2 a0 = __half22float2(((const __half2*)&u0)[0]);
        float2 b0v = __half22float2(((const __half2*)&u0)[1]);
        acc0.x = fmaf(w0, a0.x, acc0.x); acc0.y = fmaf(w0, a0.y, acc0.y);
        acc0.z = fmaf(w0, b0v.x, acc0.z); acc0.w = fmaf(w0, b0v.y, acc0.w);
    }

    float4 bv = __ldg((const float4*)b + lane);
    float4 r;
    r.x = acc0.x + acc1.x + bv.x;
    r.y = acc0.y + acc1.y + bv.y;
    r.z = acc0.z + acc1.z + bv.z;
    r.w = acc0.w + acc1.w + bv.w;
    ((float4*)out)[(size_t)n * (D_OUT / 4) + lane] = r;
}

// ---------------------------------------------------------------------------
// Launch. Inputs: x, edge_src, edge_dst, edge_w, W, b
// ---------------------------------------------------------------------------
extern "C" void kernel_launch(void* const* d_in, const int* in_sizes, int n_in,
                              void* d_out, int out_size) {
    const float* x    = (const float*)d_in[0];
    const int*   esrc = (const int*)d_in[1];
    const int*   edst = (const int*)d_in[2];
    const float* ew   = (const float*)d_in[3];
    const float* W    = (const float*)d_in[4];
    const float* b    = (const float*)d_in[5];
    float* out = (float*)d_out;

    // GEMM into g_supph (fp16)
    gemm_kernel<<<(N_NODES + 127) / 128, 256>>>(x, W);

    // CSR-by-dst build
    zero_kernel<<<(N_NODES + 255) / 256, 256>>>();
    hist_kernel<<<(N_EDGES / 4 + 255) / 256, 256>>>(edst);
    scan1_kernel<<<N_SCAN_BLOCKS, SCAN_BLOCK>>>();
    scan2_kernel<<<1, 128>>>();
    scan3_kernel<<<(N_NODES + 255) / 256, 256>>>();
    place_kernel<<<(N_EDGES + 255) / 256, 256>>>(esrc, edst, ew);

    // Pull + bias (one warp per node)
    long long pull_threads = (long long)N_NODES * 32;
    pull_kernel<<<(int)((pull_threads + 255) / 256), 256>>>(b, out);
}

// round 7
// speedup vs baseline: 2.1642x; 2.1642x over previous
#include <cuda_runtime.h>
#include <cuda_bf16.h>
#include <cuda_fp16.h>
#include <cstdint>

#define N_NODES 100000
#define N_EDGES 1600000
#define D_IN    256
#define D_OUT   128

#define SCAN_BLOCK 1024
#define N_SCAN_BLOCKS ((N_NODES + SCAN_BLOCK - 1) / SCAN_BLOCK)   // 98

typedef unsigned long long ull;

// Device scratch (static __device__ arrays only; no allocation anywhere).
__device__ __half g_supph[(size_t)N_NODES * D_OUT];    // 25.6 MB fp16 support
__device__ int   g_count[N_NODES];
__device__ int   g_offsets[N_NODES + 1];
__device__ int   g_cursor[N_NODES];
__device__ int   g_bsum[N_SCAN_BLOCKS];
__device__ int2  g_sw[N_EDGES];                        // packed (src, bits(w))

// ---------------------------------------------------------------------------
// helpers
// ---------------------------------------------------------------------------
__device__ __forceinline__ uint32_t f2tf32(float f) {
    uint32_t r;
    asm("cvt.rna.tf32.f32 %0, %1;" : "=r"(r) : "f"(f));
    return r;
}

__device__ __forceinline__ void mma_tf32(float& d0, float& d1, float& d2, float& d3,
                                         uint32_t a0, uint32_t a1, uint32_t a2, uint32_t a3,
                                         uint32_t b0, uint32_t b1) {
    asm volatile(
        "mma.sync.aligned.m16n8k8.row.col.f32.tf32.tf32.f32 "
        "{%0,%1,%2,%3}, {%4,%5,%6,%7}, {%8,%9}, {%0,%1,%2,%3};"
        : "+f"(d0), "+f"(d1), "+f"(d2), "+f"(d3)
        : "r"(a0), "r"(a1), "r"(a2), "r"(a3), "r"(b0), "r"(b1));
}

// ---------------------------------------------------------------------------
// GEMM: support = x @ W via tf32 tensor-core mma (fp32 accumulate, fp16 out).
// BM=128, BN=128, BK=8. 256 threads = 8 warps in 4(M) x 2(N): 32x64 per warp.
// Per k-step each warp issues 2x8 = 16 m16n8k8 mmas. Double-buffered smem,
// register-staged global loads, cvt to tf32 at STS time.
// Smem strides: A stride 12 -> fragment banks (12*gid+tig) all distinct;
//               B stride 136 -> (8*tig + 8*ni + gid) all distinct. Conflict-free.
// ---------------------------------------------------------------------------
__global__ __launch_bounds__(256) void gemm_tf32_kernel(const float* __restrict__ x,
                                                        const float* __restrict__ W) {
    __shared__ uint32_t As[2][128][12];   // [buf][row][k] tf32 bits, padded 8->12
    __shared__ uint32_t Bs[2][8][136];    // [buf][k][col] tf32 bits, padded 128->136

    const int tid  = threadIdx.x;
    const int wid  = tid >> 5;
    const int lane = tid & 31;
    const int gid  = lane >> 2;     // 0..7
    const int tig  = lane & 3;      // 0..3
    const int warp_m = wid & 3;     // 0..3  (32 rows each)
    const int warp_n = wid >> 2;    // 0..1  (64 cols each)
    const int block_row = blockIdx.x * 128;

    // A staging: one float4 per thread. row 0..127, k-offset 0 or 4
    const int lr = tid >> 1;
    const int lk = (tid & 1) * 4;
    // B staging: one float4 per thread. k-row 0..7, col group
    const int bk = tid >> 5;
    const int bc = (tid & 31) * 4;

    const int grow = block_row + lr;
    const bool arow_ok = (grow < N_NODES);
    const float* xrow = x + (size_t)grow * D_IN;

    float acc[2][8][4];
#pragma unroll
    for (int mi = 0; mi < 2; ++mi)
#pragma unroll
        for (int ni = 0; ni < 8; ++ni)
#pragma unroll
            for (int c = 0; c < 4; ++c) acc[mi][ni][c] = 0.0f;

    // ---- prologue: tile 0 ----
    float4 av = arow_ok ? __ldg((const float4*)(xrow + lk))
                        : make_float4(0.f, 0.f, 0.f, 0.f);
    float4 bv = __ldg((const float4*)(W + (size_t)bk * D_OUT + bc));
    As[0][lr][lk + 0] = f2tf32(av.x);
    As[0][lr][lk + 1] = f2tf32(av.y);
    As[0][lr][lk + 2] = f2tf32(av.z);
    As[0][lr][lk + 3] = f2tf32(av.w);
    Bs[0][bk][bc + 0] = f2tf32(bv.x);
    Bs[0][bk][bc + 1] = f2tf32(bv.y);
    Bs[0][bk][bc + 2] = f2tf32(bv.z);
    Bs[0][bk][bc + 3] = f2tf32(bv.w);
    __syncthreads();

    int buf = 0;
#pragma unroll 1
    for (int k0 = 0; k0 < D_IN; k0 += 8) {
        const int nxt = buf ^ 1;
        const bool has_next = (k0 + 8) < D_IN;
        float4 av2, bv2;
        if (has_next) {
            av2 = arow_ok ? __ldg((const float4*)(xrow + k0 + 8 + lk))
                          : make_float4(0.f, 0.f, 0.f, 0.f);
            bv2 = __ldg((const float4*)(W + (size_t)(k0 + 8 + bk) * D_OUT + bc));
        }

        // ---- fragment loads ----
        uint32_t afr[2][4];
#pragma unroll
        for (int mi = 0; mi < 2; ++mi) {
            const int r0 = warp_m * 32 + mi * 16 + gid;
            afr[mi][0] = As[buf][r0][tig];
            afr[mi][1] = As[buf][r0 + 8][tig];
            afr[mi][2] = As[buf][r0][tig + 4];
            afr[mi][3] = As[buf][r0 + 8][tig + 4];
        }
        uint32_t bfr[8][2];
#pragma unroll
        for (int ni = 0; ni < 8; ++ni) {
            const int c0 = warp_n * 64 + ni * 8 + gid;
            bfr[ni][0] = Bs[buf][tig][c0];
            bfr[ni][1] = Bs[buf][tig + 4][c0];
        }

        // ---- 16 mmas ----
#pragma unroll
        for (int mi = 0; mi < 2; ++mi)
#pragma unroll
            for (int ni = 0; ni < 8; ++ni)
                mma_tf32(acc[mi][ni][0], acc[mi][ni][1], acc[mi][ni][2], acc[mi][ni][3],
                         afr[mi][0], afr[mi][1], afr[mi][2], afr[mi][3],
                         bfr[ni][0], bfr[ni][1]);

        if (has_next) {
            As[nxt][lr][lk + 0] = f2tf32(av2.x);
            As[nxt][lr][lk + 1] = f2tf32(av2.y);
            As[nxt][lr][lk + 2] = f2tf32(av2.z);
            As[nxt][lr][lk + 3] = f2tf32(av2.w);
            Bs[nxt][bk][bc + 0] = f2tf32(bv2.x);
            Bs[nxt][bk][bc + 1] = f2tf32(bv2.y);
            Bs[nxt][bk][bc + 2] = f2tf32(bv2.z);
            Bs[nxt][bk][bc + 3] = f2tf32(bv2.w);
            __syncthreads();
        }
        buf = nxt;
    }

    // ---- epilogue: fp16 stores. Thread holds (rows gid,gid+8) x (cols 2tig,2tig+1)
#pragma unroll
    for (int mi = 0; mi < 2; ++mi) {
        const int r0 = block_row + warp_m * 32 + mi * 16 + gid;
        const int r1 = r0 + 8;
#pragma unroll
        for (int ni = 0; ni < 8; ++ni) {
            const int c0 = warp_n * 64 + ni * 8 + 2 * tig;
            if (r0 < N_NODES)
                *(__half2*)(g_supph + (size_t)r0 * D_OUT + c0) =
                    __floats2half2_rn(acc[mi][ni][0], acc[mi][ni][1]);
            if (r1 < N_NODES)
                *(__half2*)(g_supph + (size_t)r1 * D_OUT + c0) =
                    __floats2half2_rn(acc[mi][ni][2], acc[mi][ni][3]);
        }
    }
}

// ---------------------------------------------------------------------------
// CSR-by-dst build
// ---------------------------------------------------------------------------
__global__ void zero_kernel() {
    int i = blockIdx.x * blockDim.x + threadIdx.x;
    if (i < N_NODES) g_count[i] = 0;
}

__global__ void hist_kernel(const int* __restrict__ edst) {
    int e4 = blockIdx.x * blockDim.x + threadIdx.x;
    if (e4 < N_EDGES / 4) {
        int4 d = ((const int4*)edst)[e4];
        atomicAdd(&g_count[d.x], 1);
        atomicAdd(&g_count[d.y], 1);
        atomicAdd(&g_count[d.z], 1);
        atomicAdd(&g_count[d.w], 1);
    }
}

__global__ __launch_bounds__(SCAN_BLOCK) void scan1_kernel() {
    __shared__ int warp_sums[32];
    const int t = threadIdx.x;
    const int idx = blockIdx.x * SCAN_BLOCK + t;
    const int lane = t & 31;
    const int wrp  = t >> 5;
    int v = (idx < N_NODES) ? g_count[idx] : 0;
    int incl = v;
#pragma unroll
    for (int off = 1; off < 32; off <<= 1) {
        int n = __shfl_up_sync(0xffffffffu, incl, off);
        if (lane >= off) incl += n;
    }
    if (lane == 31) warp_sums[wrp] = incl;
    __syncthreads();
    if (t < 32) {
        int s = warp_sums[t];
        int si = s;
#pragma unroll
        for (int off = 1; off < 32; off <<= 1) {
            int n = __shfl_up_sync(0xffffffffu, si, off);
            if (t >= off) si += n;
        }
        warp_sums[t] = si - s;   // exclusive warp prefix
    }
    __syncthreads();
    int excl = incl - v + warp_sums[wrp];
    if (idx < N_NODES) g_offsets[idx] = excl;
    if (t == SCAN_BLOCK - 1) g_bsum[blockIdx.x] = excl + v;
}

__global__ void scan2_kernel() {
    __shared__ int ws[4];
    const int t = threadIdx.x;          // 128 threads
    const int lane = t & 31, wrp = t >> 5;
    int v = (t < N_SCAN_BLOCKS) ? g_bsum[t] : 0;
    int incl = v;
#pragma unroll
    for (int off = 1; off < 32; off <<= 1) {
        int n = __shfl_up_sync(0xffffffffu, incl, off);
        if (lane >= off) incl += n;
    }
    if (lane == 31) ws[wrp] = incl;
    __syncthreads();
    int add = 0;
#pragma unroll
    for (int w = 0; w < 4; ++w) add += (w < wrp) ? ws[w] : 0;
    if (t < N_SCAN_BLOCKS) g_bsum[t] = incl - v + add;   // exclusive
}

__global__ void scan3_kernel() {
    int idx = blockIdx.x * blockDim.x + threadIdx.x;
    if (idx < N_NODES) {
        int off = g_offsets[idx] + g_bsum[idx / SCAN_BLOCK];
        g_offsets[idx] = off;
        g_cursor[idx]  = off;
    }
    if (idx == 0) g_offsets[N_NODES] = N_EDGES;
}

__global__ void place_kernel(const int* __restrict__ esrc,
                             const int* __restrict__ edst,
                             const float* __restrict__ ew) {
    int e = blockIdx.x * blockDim.x + threadIdx.x;
    if (e >= N_EDGES) return;
    int d = edst[e];
    int pos = atomicAdd(&g_cursor[d], 1);
    g_sw[pos] = make_int2(esrc[e], __float_as_int(ew[e]));
}

// ---------------------------------------------------------------------------
// Pull: warp per dst node, 4 fp16 gathers in flight (8B/lane), fp32 accumulate.
// out[n] = b + sum_e w_e * support[src_e]. No atomics.
// ---------------------------------------------------------------------------
__global__ __launch_bounds__(256) void pull_kernel(const float* __restrict__ b,
                                                   float* __restrict__ out) {
    const int n    = (blockIdx.x * blockDim.x + threadIdx.x) >> 5;
    const int lane = threadIdx.x & 31;
    if (n >= N_NODES) return;

    const int start = __ldg(&g_offsets[n]);
    const int end   = __ldg(&g_offsets[n + 1]);

    float4 acc0 = make_float4(0.f, 0.f, 0.f, 0.f);
    float4 acc1 = make_float4(0.f, 0.f, 0.f, 0.f);
    const ull* sup = (const ull*)g_supph;   // 4 halves per 8B
    const int loff = lane;

    int j = start;
    for (; j + 3 < end; j += 4) {
        int2 sw0 = __ldg(&g_sw[j]);
        int2 sw1 = __ldg(&g_sw[j + 1]);
        int2 sw2 = __ldg(&g_sw[j + 2]);
        int2 sw3 = __ldg(&g_sw[j + 3]);
        ull u0 = __ldg(sup + (size_t)sw0.x * (D_OUT / 4) + loff);
        ull u1 = __ldg(sup + (size_t)sw1.x * (D_OUT / 4) + loff);
        ull u2 = __ldg(sup + (size_t)sw2.x * (D_OUT / 4) + loff);
        ull u3 = __ldg(sup + (size_t)sw3.x * (D_OUT / 4) + loff);
        float w0 = __int_as_float(sw0.y), w1 = __int_as_float(sw1.y);
        float w2 = __int_as_float(sw2.y), w3 = __int_as_float(sw3.y);

        float2 a0 = __half22float2(((const __half2*)&u0)[0]);
        float2 b0v = __half22float2(((const __half2*)&u0)[1]);
        float2 a1 = __half22float2(((const __half2*)&u1)[0]);
        float2 b1v = __half22float2(((const __half2*)&u1)[1]);
        float2 a2 = __half22float2(((const __half2*)&u2)[0]);
        float2 b2v = __half22float2(((const __half2*)&u2)[1]);
        float2 a3 = __half22float2(((const __half2*)&u3)[0]);
        float2 b3v = __half22float2(((const __half2*)&u3)[1]);

        acc0.x = fmaf(w0, a0.x, acc0.x); acc0.y = fmaf(w0, a0.y, acc0.y);
        acc0.z = fmaf(w0, b0v.x, acc0.z); acc0.w = fmaf(w0, b0v.y, acc0.w);
        acc1.x = fmaf(w1, a1.x, acc1.x); acc1.y = fmaf(w1, a1.y, acc1.y);
        acc1.z = fmaf(w1, b1v.x, acc1.z); acc1.w = fmaf(w1, b1v.y, acc1.w);
        acc0.x = fmaf(w2, a2.x, acc0.x); acc0.y = fmaf(w2, a2.y, acc0.y);
        acc0.z = fmaf(w2, b2v.x, acc0.z); acc0.w = fmaf(w2, b2v.y, acc0.w);
        acc1.x = fmaf(w3, a3.x, acc1.x); acc1.y = fmaf(w3, a3.y, acc1.y);
        acc1.z = fmaf(w3, b3v.x, acc1.z); acc1.w = fmaf(w3, b3v.y, acc1.w);
    }
    for (; j < end; ++j) {
        int2 sw0 = __ldg(&g_sw[j]);
        float w0 = __int_as_float(sw0.y);
        ull u0 = __ldg(sup + (size_t)sw0.x * (D_OUT / 4) + loff);
        float2 a0 = __half22float2(((const __half2*)&u0)[0]);
        float2 b0v = __half22float2(((const __half2*)&u0)[1]);
        acc0.x = fmaf(w0, a0.x, acc0.x); acc0.y = fmaf(w0, a0.y, acc0.y);
        acc0.z = fmaf(w0, b0v.x, acc0.z); acc0.w = fmaf(w0, b0v.y, acc0.w);
    }

    float4 bv = __ldg((const float4*)b + lane);
    float4 r;
    r.x = acc0.x + acc1.x + bv.x;
    r.y = acc0.y + acc1.y + bv.y;
    r.z = acc0.z + acc1.z + bv.z;
    r.w = acc0.w + acc1.w + bv.w;
    ((float4*)out)[(size_t)n * (D_OUT / 4) + lane] = r;
}

// ---------------------------------------------------------------------------
// Launch. Inputs: x, edge_src, edge_dst, edge_w, W, b
// ---------------------------------------------------------------------------
extern "C" void kernel_launch(void* const* d_in, const int* in_sizes, int n_in,
                              void* d_out, int out_size) {
    const float* x    = (const float*)d_in[0];
    const int*   esrc = (const int*)d_in[1];
    const int*   edst = (const int*)d_in[2];
    const float* ew   = (const float*)d_in[3];
    const float* W    = (const float*)d_in[4];
    const float* b    = (const float*)d_in[5];
    float* out = (float*)d_out;

    // GEMM into g_supph (tf32 tensor core, fp16 output)
    gemm_tf32_kernel<<<(N_NODES + 127) / 128, 256>>>(x, W);

    // CSR-by-dst build
    zero_kernel<<<(N_NODES + 255) / 256, 256>>>();
    hist_kernel<<<(N_EDGES / 4 + 255) / 256, 256>>>(edst);
    scan1_kernel<<<N_SCAN_BLOCKS, SCAN_BLOCK>>>();
    scan2_kernel<<<1, 128>>>();
    scan3_kernel<<<(N_NODES + 255) / 256, 256>>>();
    place_kernel<<<(N_EDGES + 255) / 256, 256>>>(esrc, edst, ew);

    // Pull + bias (one warp per node)
    long long pull_threads = (long long)N_NODES * 32;
    pull_kernel<<<(int)((pull_threads + 255) / 256), 256>>>(b, out);
}

// round 8
// speedup vs baseline: 2.4504x; 1.1322x over previous
#include <cuda_runtime.h>
#include <cuda_bf16.h>
#include <cuda_fp16.h>
#include <cstdint>

#define N_NODES 100000
#define N_EDGES 1600000
#define D_IN    256
#define D_OUT   128

#define SCAN_BLOCK 1024
#define N_SCAN_BLOCKS ((N_NODES + SCAN_BLOCK - 1) / SCAN_BLOCK)   // 98

typedef unsigned long long ull;

// Device scratch (static __device__ arrays only; no allocation anywhere).
__device__ __half g_supph[(size_t)N_NODES * D_OUT];    // 25.6 MB fp16 support
__device__ int   g_count[N_NODES];
__device__ int   g_offsets[N_NODES + 1];
__device__ int   g_cursor[N_NODES];
__device__ int   g_bsum[N_SCAN_BLOCKS];
__device__ int2  g_sw[N_EDGES];                        // packed (src, bits(w))

// ---------------------------------------------------------------------------
// helpers
// ---------------------------------------------------------------------------
__device__ __forceinline__ uint32_t f2tf32(float f) {
    uint32_t r;
    asm("cvt.rna.tf32.f32 %0, %1;" : "=r"(r) : "f"(f));
    return r;
}

__device__ __forceinline__ void mma_tf32(float& d0, float& d1, float& d2, float& d3,
                                         uint32_t a0, uint32_t a1, uint32_t a2, uint32_t a3,
                                         uint32_t b0, uint32_t b1) {
    asm volatile(
        "mma.sync.aligned.m16n8k8.row.col.f32.tf32.tf32.f32 "
        "{%0,%1,%2,%3}, {%4,%5,%6,%7}, {%8,%9}, {%0,%1,%2,%3};"
        : "+f"(d0), "+f"(d1), "+f"(d2), "+f"(d3)
        : "r"(a0), "r"(a1), "r"(a2), "r"(a3), "r"(b0), "r"(b1));
}

// ---------------------------------------------------------------------------
// GEMM: support = x @ W via tf32 mma. BM=128, BN=128, BK=16.
// 256 threads = 8 warps in 4(M) x 2(N): 32x64 per warp, 2x8 mmas per k-sub,
// 2 k-subs per buffered tile (32 mmas per __syncthreads).
// A stride 20 / B stride 136: fragment LDS conflict-free.
// ---------------------------------------------------------------------------
__global__ __launch_bounds__(256) void gemm_tf32_kernel(const float* __restrict__ x,
                                                        const float* __restrict__ W) {
    __shared__ uint32_t As[2][128][20];   // [buf][row][k0..15] pad 16->20
    __shared__ uint32_t Bs[2][16][136];   // [buf][k][col] pad 128->136

    const int tid  = threadIdx.x;
    const int wid  = tid >> 5;
    const int lane = tid & 31;
    const int gid  = lane >> 2;     // 0..7
    const int tig  = lane & 3;      // 0..3
    const int warp_m = wid & 3;     // 0..3  (32 rows each)
    const int warp_n = wid >> 2;    // 0..1  (64 cols each)
    const int block_row = blockIdx.x * 128;

    // A staging: 2 float4 per thread: row lr, k-offsets lk, lk+4
    const int lr = tid >> 1;
    const int lk = (tid & 1) * 8;
    // B staging: 2 float4 per thread: k-rows bk, bk+8
    const int bk = tid >> 5;
    const int bc = (tid & 31) * 4;

    const int grow = block_row + lr;
    const bool arow_ok = (grow < N_NODES);
    const float* xrow = x + (size_t)grow * D_IN;

    float acc[2][8][4];
#pragma unroll
    for (int mi = 0; mi < 2; ++mi)
#pragma unroll
        for (int ni = 0; ni < 8; ++ni)
#pragma unroll
            for (int c = 0; c < 4; ++c) acc[mi][ni][c] = 0.0f;

    // ---- staging store helper (convert + vector STS) ----
    auto stage = [&](int b, float4 a0, float4 a1, float4 w0, float4 w1) {
        uint4 t0 = make_uint4(f2tf32(a0.x), f2tf32(a0.y), f2tf32(a0.z), f2tf32(a0.w));
        uint4 t1 = make_uint4(f2tf32(a1.x), f2tf32(a1.y), f2tf32(a1.z), f2tf32(a1.w));
        *(uint4*)&As[b][lr][lk]     = t0;
        *(uint4*)&As[b][lr][lk + 4] = t1;
        uint4 u0 = make_uint4(f2tf32(w0.x), f2tf32(w0.y), f2tf32(w0.z), f2tf32(w0.w));
        uint4 u1 = make_uint4(f2tf32(w1.x), f2tf32(w1.y), f2tf32(w1.z), f2tf32(w1.w));
        *(uint4*)&Bs[b][bk][bc]     = u0;
        *(uint4*)&Bs[b][bk + 8][bc] = u1;
    };

    // ---- prologue: tile 0 ----
    {
        float4 a0 = arow_ok ? __ldg((const float4*)(xrow + lk))     : make_float4(0,0,0,0);
        float4 a1 = arow_ok ? __ldg((const float4*)(xrow + lk + 4)) : make_float4(0,0,0,0);
        float4 w0 = __ldg((const float4*)(W + (size_t)bk * D_OUT + bc));
        float4 w1 = __ldg((const float4*)(W + (size_t)(bk + 8) * D_OUT + bc));
        stage(0, a0, a1, w0, w1);
    }
    __syncthreads();

    int buf = 0;
#pragma unroll 1
    for (int k0 = 0; k0 < D_IN; k0 += 16) {
        const int nxt = buf ^ 1;
        const bool has_next = (k0 + 16) < D_IN;
        float4 a0n, a1n, w0n, w1n;
        if (has_next) {
            a0n = arow_ok ? __ldg((const float4*)(xrow + k0 + 16 + lk))     : make_float4(0,0,0,0);
            a1n = arow_ok ? __ldg((const float4*)(xrow + k0 + 16 + lk + 4)) : make_float4(0,0,0,0);
            w0n = __ldg((const float4*)(W + (size_t)(k0 + 16 + bk) * D_OUT + bc));
            w1n = __ldg((const float4*)(W + (size_t)(k0 + 16 + bk + 8) * D_OUT + bc));
        }

#pragma unroll
        for (int ks = 0; ks < 16; ks += 8) {
            uint32_t afr[2][4];
#pragma unroll
            for (int mi = 0; mi < 2; ++mi) {
                const int r0 = warp_m * 32 + mi * 16 + gid;
                afr[mi][0] = As[buf][r0][ks + tig];
                afr[mi][1] = As[buf][r0 + 8][ks + tig];
                afr[mi][2] = As[buf][r0][ks + tig + 4];
                afr[mi][3] = As[buf][r0 + 8][ks + tig + 4];
            }
            uint32_t bfr[8][2];
#pragma unroll
            for (int ni = 0; ni < 8; ++ni) {
                const int c0 = warp_n * 64 + ni * 8 + gid;
                bfr[ni][0] = Bs[buf][ks + tig][c0];
                bfr[ni][1] = Bs[buf][ks + tig + 4][c0];
            }
#pragma unroll
            for (int mi = 0; mi < 2; ++mi)
#pragma unroll
                for (int ni = 0; ni < 8; ++ni)
                    mma_tf32(acc[mi][ni][0], acc[mi][ni][1], acc[mi][ni][2], acc[mi][ni][3],
                             afr[mi][0], afr[mi][1], afr[mi][2], afr[mi][3],
                             bfr[ni][0], bfr[ni][1]);
        }

        if (has_next) {
            stage(nxt, a0n, a1n, w0n, w1n);
            __syncthreads();
        }
        buf = nxt;
    }

    // ---- epilogue: fp16 stores. Thread holds (rows gid,gid+8) x (cols 2tig,2tig+1)
#pragma unroll
    for (int mi = 0; mi < 2; ++mi) {
        const int r0 = block_row + warp_m * 32 + mi * 16 + gid;
        const int r1 = r0 + 8;
#pragma unroll
        for (int ni = 0; ni < 8; ++ni) {
            const int c0 = warp_n * 64 + ni * 8 + 2 * tig;
            if (r0 < N_NODES)
                *(__half2*)(g_supph + (size_t)r0 * D_OUT + c0) =
                    __floats2half2_rn(acc[mi][ni][0], acc[mi][ni][1]);
            if (r1 < N_NODES)
                *(__half2*)(g_supph + (size_t)r1 * D_OUT + c0) =
                    __floats2half2_rn(acc[mi][ni][2], acc[mi][ni][3]);
        }
    }
}

// ---------------------------------------------------------------------------
// CSR-by-dst build
// ---------------------------------------------------------------------------
__global__ void zero_kernel() {
    int i = blockIdx.x * blockDim.x + threadIdx.x;
    if (i < N_NODES) g_count[i] = 0;
}

__global__ void hist_kernel(const int* __restrict__ edst) {
    int e4 = blockIdx.x * blockDim.x + threadIdx.x;
    if (e4 < N_EDGES / 4) {
        int4 d = ((const int4*)edst)[e4];
        atomicAdd(&g_count[d.x], 1);
        atomicAdd(&g_count[d.y], 1);
        atomicAdd(&g_count[d.z], 1);
        atomicAdd(&g_count[d.w], 1);
    }
}

__global__ __launch_bounds__(SCAN_BLOCK) void scan1_kernel() {
    __shared__ int warp_sums[32];
    const int t = threadIdx.x;
    const int idx = blockIdx.x * SCAN_BLOCK + t;
    const int lane = t & 31;
    const int wrp  = t >> 5;
    int v = (idx < N_NODES) ? g_count[idx] : 0;
    int incl = v;
#pragma unroll
    for (int off = 1; off < 32; off <<= 1) {
        int n = __shfl_up_sync(0xffffffffu, incl, off);
        if (lane >= off) incl += n;
    }
    if (lane == 31) warp_sums[wrp] = incl;
    __syncthreads();
    if (t < 32) {
        int s = warp_sums[t];
        int si = s;
#pragma unroll
        for (int off = 1; off < 32; off <<= 1) {
            int n = __shfl_up_sync(0xffffffffu, si, off);
            if (t >= off) si += n;
        }
        warp_sums[t] = si - s;   // exclusive warp prefix
    }
    __syncthreads();
    int excl = incl - v + warp_sums[wrp];
    if (idx < N_NODES) g_offsets[idx] = excl;
    if (t == SCAN_BLOCK - 1) g_bsum[blockIdx.x] = excl + v;
}

__global__ void scan2_kernel() {
    __shared__ int ws[4];
    const int t = threadIdx.x;          // 128 threads
    const int lane = t & 31, wrp = t >> 5;
    int v = (t < N_SCAN_BLOCKS) ? g_bsum[t] : 0;
    int incl = v;
#pragma unroll
    for (int off = 1; off < 32; off <<= 1) {
        int n = __shfl_up_sync(0xffffffffu, incl, off);
        if (lane >= off) incl += n;
    }
    if (lane == 31) ws[wrp] = incl;
    __syncthreads();
    int add = 0;
#pragma unroll
    for (int w = 0; w < 4; ++w) add += (w < wrp) ? ws[w] : 0;
    if (t < N_SCAN_BLOCKS) g_bsum[t] = incl - v + add;   // exclusive
}

__global__ void scan3_kernel() {
    int idx = blockIdx.x * blockDim.x + threadIdx.x;
    if (idx < N_NODES) {
        int off = g_offsets[idx] + g_bsum[idx / SCAN_BLOCK];
        g_offsets[idx] = off;
        g_cursor[idx]  = off;
    }
    if (idx == 0) g_offsets[N_NODES] = N_EDGES;
}

__global__ void place_kernel(const int* __restrict__ esrc,
                             const int* __restrict__ edst,
                             const float* __restrict__ ew) {
    int e4 = blockIdx.x * blockDim.x + threadIdx.x;
    if (e4 >= N_EDGES / 4) return;
    int4   s = ((const int4*)esrc)[e4];
    int4   d = ((const int4*)edst)[e4];
    float4 w = ((const float4*)ew)[e4];
    int p0 = atomicAdd(&g_cursor[d.x], 1);
    g_sw[p0] = make_int2(s.x, __float_as_int(w.x));
    int p1 = atomicAdd(&g_cursor[d.y], 1);
    g_sw[p1] = make_int2(s.y, __float_as_int(w.y));
    int p2 = atomicAdd(&g_cursor[d.z], 1);
    g_sw[p2] = make_int2(s.z, __float_as_int(w.z));
    int p3 = atomicAdd(&g_cursor[d.w], 1);
    g_sw[p3] = make_int2(s.w, __float_as_int(w.w));
}

// ---------------------------------------------------------------------------
// Pull: HALF-warp per dst node (16 lanes x 16B = 256B row), 4 edges in flight.
// fp16 gather, fp32 accumulate, bias fused. No atomics.
// ---------------------------------------------------------------------------
__global__ __launch_bounds__(256) void pull_kernel(const float* __restrict__ b,
                                                   float* __restrict__ out) {
    const int n   = (blockIdx.x * blockDim.x + threadIdx.x) >> 4;   // halfwarp id
    const int l16 = threadIdx.x & 15;
    if (n >= N_NODES) return;

    const int start = __ldg(&g_offsets[n]);
    const int end   = __ldg(&g_offsets[n + 1]);

    float acc[8];
#pragma unroll
    for (int i = 0; i < 8; ++i) acc[i] = 0.0f;

    const uint4* sup = (const uint4*)g_supph;   // 8 halves per 16B; 16 uint4 per row

    int j = start;
    for (; j + 3 < end; j += 4) {
        int2 sw0 = __ldg(&g_sw[j]);
        int2 sw1 = __ldg(&g_sw[j + 1]);
        int2 sw2 = __ldg(&g_sw[j + 2]);
        int2 sw3 = __ldg(&g_sw[j + 3]);
        uint4 u0 = __ldg(sup + (size_t)sw0.x * 16 + l16);
        uint4 u1 = __ldg(sup + (size_t)sw1.x * 16 + l16);
        uint4 u2 = __ldg(sup + (size_t)sw2.x * 16 + l16);
        uint4 u3 = __ldg(sup + (size_t)sw3.x * 16 + l16);
        float w0 = __int_as_float(sw0.y), w1 = __int_as_float(sw1.y);
        float w2 = __int_as_float(sw2.y), w3 = __int_as_float(sw3.y);

#pragma unroll
        for (int h = 0; h < 4; ++h) {
            float2 f0 = __half22float2(((const __half2*)&u0)[h]);
            float2 f1 = __half22float2(((const __half2*)&u1)[h]);
            float2 f2 = __half22float2(((const __half2*)&u2)[h]);
            float2 f3 = __half22float2(((const __half2*)&u3)[h]);
            acc[2*h]   = fmaf(w0, f0.x, acc[2*h]);
            acc[2*h+1] = fmaf(w0, f0.y, acc[2*h+1]);
            acc[2*h]   = fmaf(w1, f1.x, acc[2*h]);
            acc[2*h+1] = fmaf(w1, f1.y, acc[2*h+1]);
            acc[2*h]   = fmaf(w2, f2.x, acc[2*h]);
            acc[2*h+1] = fmaf(w2, f2.y, acc[2*h+1]);
            acc[2*h]   = fmaf(w3, f3.x, acc[2*h]);
            acc[2*h+1] = fmaf(w3, f3.y, acc[2*h+1]);
        }
    }
    for (; j < end; ++j) {
        int2 sw0 = __ldg(&g_sw[j]);
        float w0 = __int_as_float(sw0.y);
        uint4 u0 = __ldg(sup + (size_t)sw0.x * 16 + l16);
#pragma unroll
        for (int h = 0; h < 4; ++h) {
            float2 f0 = __half22float2(((const __half2*)&u0)[h]);
            acc[2*h]   = fmaf(w0, f0.x, acc[2*h]);
            acc[2*h+1] = fmaf(w0, f0.y, acc[2*h+1]);
        }
    }

    float4 bv0 = __ldg((const float4*)b + 2 * l16);
    float4 bv1 = __ldg((const float4*)b + 2 * l16 + 1);
    float4 r0 = make_float4(acc[0] + bv0.x, acc[1] + bv0.y, acc[2] + bv0.z, acc[3] + bv0.w);
    float4 r1 = make_float4(acc[4] + bv1.x, acc[5] + bv1.y, acc[6] + bv1.z, acc[7] + bv1.w);
    float4* op = (float4*)out + (size_t)n * (D_OUT / 4) + 2 * l16;
    op[0] = r0;
    op[1] = r1;
}

// ---------------------------------------------------------------------------
// Launch. Inputs: x, edge_src, edge_dst, edge_w, W, b
// ---------------------------------------------------------------------------
extern "C" void kernel_launch(void* const* d_in, const int* in_sizes, int n_in,
                              void* d_out, int out_size) {
    const float* x    = (const float*)d_in[0];
    const int*   esrc = (const int*)d_in[1];
    const int*   edst = (const int*)d_in[2];
    const float* ew   = (const float*)d_in[3];
    const float* W    = (const float*)d_in[4];
    const float* b    = (const float*)d_in[5];
    float* out = (float*)d_out;

    // GEMM into g_supph (tf32 tensor core, fp16 output)
    gemm_tf32_kernel<<<(N_NODES + 127) / 128, 256>>>(x, W);

    // CSR-by-dst build
    zero_kernel<<<(N_NODES + 255) / 256, 256>>>();
    hist_kernel<<<(N_EDGES / 4 + 255) / 256, 256>>>(edst);
    scan1_kernel<<<N_SCAN_BLOCKS, SCAN_BLOCK>>>();
    scan2_kernel<<<1, 128>>>();
    scan3_kernel<<<(N_NODES + 255) / 256, 256>>>();
    place_kernel<<<(N_EDGES / 4 + 255) / 256, 256>>>(esrc, edst, ew);

    // Pull + bias (half-warp per node)
    long long pull_threads = (long long)N_NODES * 16;
    pull_kernel<<<(int)((pull_threads + 255) / 256), 256>>>(b, out);
}

// round 9
// speedup vs baseline: 2.7474x; 1.1212x over previous
#include <cuda_runtime.h>
#include <cuda_bf16.h>
#include <cuda_fp16.h>
#include <cstdint>

#define N_NODES 100000
#define N_EDGES 1600000
#define D_IN    256
#define D_OUT   128

#define SCAN_BLOCK 1024
#define N_SCAN_BLOCKS ((N_NODES + SCAN_BLOCK - 1) / SCAN_BLOCK)   // 98

typedef unsigned long long ull;

// Device scratch (static __device__ arrays only; no allocation anywhere).
// NOTE: g_count is loader-zero-initialized and re-zeroed by scan1 on every
// call, so hist always sees zeros (invariant maintained across calls/replays).
__device__ __half g_supph[(size_t)N_NODES * D_OUT];    // 25.6 MB fp16 support
__device__ int   g_count[N_NODES];
__device__ int   g_offsets[N_NODES + 1];
__device__ int   g_cursor[N_NODES];
__device__ int   g_bsum[N_SCAN_BLOCKS];
__device__ int2  g_sw[N_EDGES];                        // packed (src, bits(w))

// ---------------------------------------------------------------------------
// helpers
// ---------------------------------------------------------------------------
__device__ __forceinline__ uint32_t f2tf32(float f) {
    uint32_t r;
    asm("cvt.rna.tf32.f32 %0, %1;" : "=r"(r) : "f"(f));
    return r;
}

__device__ __forceinline__ void mma_tf32(float& d0, float& d1, float& d2, float& d3,
                                         uint32_t a0, uint32_t a1, uint32_t a2, uint32_t a3,
                                         uint32_t b0, uint32_t b1) {
    asm volatile(
        "mma.sync.aligned.m16n8k8.row.col.f32.tf32.tf32.f32 "
        "{%0,%1,%2,%3}, {%4,%5,%6,%7}, {%8,%9}, {%0,%1,%2,%3};"
        : "+f"(d0), "+f"(d1), "+f"(d2), "+f"(d3)
        : "r"(a0), "r"(a1), "r"(a2), "r"(a3), "r"(b0), "r"(b1));
}

// ---------------------------------------------------------------------------
// GEMM: support = x @ W via tf32 mma. BM=128, BN=128, BK=16.
// 256 threads = 8 warps in 4(M) x 2(N): 32x64 per warp, 32 mmas per barrier.
// A stride 20 / B stride 136: fragment LDS conflict-free.
// ---------------------------------------------------------------------------
__global__ __launch_bounds__(256) void gemm_tf32_kernel(const float* __restrict__ x,
                                                        const float* __restrict__ W) {
    __shared__ uint32_t As[2][128][20];   // [buf][row][k0..15] pad 16->20
    __shared__ uint32_t Bs[2][16][136];   // [buf][k][col] pad 128->136

    const int tid  = threadIdx.x;
    const int wid  = tid >> 5;
    const int lane = tid & 31;
    const int gid  = lane >> 2;     // 0..7
    const int tig  = lane & 3;      // 0..3
    const int warp_m = wid & 3;     // 0..3  (32 rows each)
    const int warp_n = wid >> 2;    // 0..1  (64 cols each)
    const int block_row = blockIdx.x * 128;

    const int lr = tid >> 1;
    const int lk = (tid & 1) * 8;
    const int bk = tid >> 5;
    const int bc = (tid & 31) * 4;

    const int grow = block_row + lr;
    const bool arow_ok = (grow < N_NODES);
    const float* xrow = x + (size_t)grow * D_IN;

    float acc[2][8][4];
#pragma unroll
    for (int mi = 0; mi < 2; ++mi)
#pragma unroll
        for (int ni = 0; ni < 8; ++ni)
#pragma unroll
            for (int c = 0; c < 4; ++c) acc[mi][ni][c] = 0.0f;

    auto stage = [&](int b, float4 a0, float4 a1, float4 w0, float4 w1) {
        uint4 t0 = make_uint4(f2tf32(a0.x), f2tf32(a0.y), f2tf32(a0.z), f2tf32(a0.w));
        uint4 t1 = make_uint4(f2tf32(a1.x), f2tf32(a1.y), f2tf32(a1.z), f2tf32(a1.w));
        *(uint4*)&As[b][lr][lk]     = t0;
        *(uint4*)&As[b][lr][lk + 4] = t1;
        uint4 u0 = make_uint4(f2tf32(w0.x), f2tf32(w0.y), f2tf32(w0.z), f2tf32(w0.w));
        uint4 u1 = make_uint4(f2tf32(w1.x), f2tf32(w1.y), f2tf32(w1.z), f2tf32(w1.w));
        *(uint4*)&Bs[b][bk][bc]     = u0;
        *(uint4*)&Bs[b][bk + 8][bc] = u1;
    };

    {
        float4 a0 = arow_ok ? __ldg((const float4*)(xrow + lk))     : make_float4(0,0,0,0);
        float4 a1 = arow_ok ? __ldg((const float4*)(xrow + lk + 4)) : make_float4(0,0,0,0);
        float4 w0 = __ldg((const float4*)(W + (size_t)bk * D_OUT + bc));
        float4 w1 = __ldg((const float4*)(W + (size_t)(bk + 8) * D_OUT + bc));
        stage(0, a0, a1, w0, w1);
    }
    __syncthreads();

    int buf = 0;
#pragma unroll 1
    for (int k0 = 0; k0 < D_IN; k0 += 16) {
        const int nxt = buf ^ 1;
        const bool has_next = (k0 + 16) < D_IN;
        float4 a0n, a1n, w0n, w1n;
        if (has_next) {
            a0n = arow_ok ? __ldg((const float4*)(xrow + k0 + 16 + lk))     : make_float4(0,0,0,0);
            a1n = arow_ok ? __ldg((const float4*)(xrow + k0 + 16 + lk + 4)) : make_float4(0,0,0,0);
            w0n = __ldg((const float4*)(W + (size_t)(k0 + 16 + bk) * D_OUT + bc));
            w1n = __ldg((const float4*)(W + (size_t)(k0 + 16 + bk + 8) * D_OUT + bc));
        }

#pragma unroll
        for (int ks = 0; ks < 16; ks += 8) {
            uint32_t afr[2][4];
#pragma unroll
            for (int mi = 0; mi < 2; ++mi) {
                const int r0 = warp_m * 32 + mi * 16 + gid;
                afr[mi][0] = As[buf][r0][ks + tig];
                afr[mi][1] = As[buf][r0 + 8][ks + tig];
                afr[mi][2] = As[buf][r0][ks + tig + 4];
                afr[mi][3] = As[buf][r0 + 8][ks + tig + 4];
            }
            uint32_t bfr[8][2];
#pragma unroll
            for (int ni = 0; ni < 8; ++ni) {
                const int c0 = warp_n * 64 + ni * 8 + gid;
                bfr[ni][0] = Bs[buf][ks + tig][c0];
                bfr[ni][1] = Bs[buf][ks + tig + 4][c0];
            }
#pragma unroll
            for (int mi = 0; mi < 2; ++mi)
#pragma unroll
                for (int ni = 0; ni < 8; ++ni)
                    mma_tf32(acc[mi][ni][0], acc[mi][ni][1], acc[mi][ni][2], acc[mi][ni][3],
                             afr[mi][0], afr[mi][1], afr[mi][2], afr[mi][3],
                             bfr[ni][0], bfr[ni][1]);
        }

        if (has_next) {
            stage(nxt, a0n, a1n, w0n, w1n);
            __syncthreads();
        }
        buf = nxt;
    }

#pragma unroll
    for (int mi = 0; mi < 2; ++mi) {
        const int r0 = block_row + warp_m * 32 + mi * 16 + gid;
        const int r1 = r0 + 8;
#pragma unroll
        for (int ni = 0; ni < 8; ++ni) {
            const int c0 = warp_n * 64 + ni * 8 + 2 * tig;
            if (r0 < N_NODES)
                *(__half2*)(g_supph + (size_t)r0 * D_OUT + c0) =
                    __floats2half2_rn(acc[mi][ni][0], acc[mi][ni][1]);
            if (r1 < N_NODES)
                *(__half2*)(g_supph + (size_t)r1 * D_OUT + c0) =
                    __floats2half2_rn(acc[mi][ni][2], acc[mi][ni][3]);
        }
    }
}

// ---------------------------------------------------------------------------
// CSR-by-dst build (g_count arrives zeroed; scan1 re-zeros it after reading)
// ---------------------------------------------------------------------------
__global__ void hist_kernel(const int* __restrict__ edst) {
    int e4 = blockIdx.x * blockDim.x + threadIdx.x;
    if (e4 < N_EDGES / 4) {
        int4 d = ((const int4*)edst)[e4];
        atomicAdd(&g_count[d.x], 1);
        atomicAdd(&g_count[d.y], 1);
        atomicAdd(&g_count[d.z], 1);
        atomicAdd(&g_count[d.w], 1);
    }
}

__global__ __launch_bounds__(SCAN_BLOCK) void scan1_kernel() {
    __shared__ int warp_sums[32];
    const int t = threadIdx.x;
    const int idx = blockIdx.x * SCAN_BLOCK + t;
    const int lane = t & 31;
    const int wrp  = t >> 5;
    int v = (idx < N_NODES) ? g_count[idx] : 0;
    if (idx < N_NODES) g_count[idx] = 0;     // restore invariant for next call
    int incl = v;
#pragma unroll
    for (int off = 1; off < 32; off <<= 1) {
        int n = __shfl_up_sync(0xffffffffu, incl, off);
        if (lane >= off) incl += n;
    }
    if (lane == 31) warp_sums[wrp] = incl;
    __syncthreads();
    if (t < 32) {
        int s = warp_sums[t];
        int si = s;
#pragma unroll
        for (int off = 1; off < 32; off <<= 1) {
            int n = __shfl_up_sync(0xffffffffu, si, off);
            if (t >= off) si += n;
        }
        warp_sums[t] = si - s;   // exclusive warp prefix
    }
    __syncthreads();
    int excl = incl - v + warp_sums[wrp];
    if (idx < N_NODES) g_offsets[idx] = excl;
    if (t == SCAN_BLOCK - 1) g_bsum[blockIdx.x] = excl + v;
}

__global__ void scan2_kernel() {
    __shared__ int ws[4];
    const int t = threadIdx.x;          // 128 threads
    const int lane = t & 31, wrp = t >> 5;
    int v = (t < N_SCAN_BLOCKS) ? g_bsum[t] : 0;
    int incl = v;
#pragma unroll
    for (int off = 1; off < 32; off <<= 1) {
        int n = __shfl_up_sync(0xffffffffu, incl, off);
        if (lane >= off) incl += n;
    }
    if (lane == 31) ws[wrp] = incl;
    __syncthreads();
    int add = 0;
#pragma unroll
    for (int w = 0; w < 4; ++w) add += (w < wrp) ? ws[w] : 0;
    if (t < N_SCAN_BLOCKS) g_bsum[t] = incl - v + add;   // exclusive
}

__global__ void scan3_kernel() {
    int idx = blockIdx.x * blockDim.x + threadIdx.x;
    if (idx < N_NODES) {
        int off = g_offsets[idx] + g_bsum[idx / SCAN_BLOCK];
        g_offsets[idx] = off;
        g_cursor[idx]  = off;
    }
    if (idx == 0) g_offsets[N_NODES] = N_EDGES;
}

__global__ void place_kernel(const int* __restrict__ esrc,
                             const int* __restrict__ edst,
                             const float* __restrict__ ew) {
    int e4 = blockIdx.x * blockDim.x + threadIdx.x;
    if (e4 >= N_EDGES / 4) return;
    int4   s = ((const int4*)esrc)[e4];
    int4   d = ((const int4*)edst)[e4];
    float4 w = ((const float4*)ew)[e4];
    int p0 = atomicAdd(&g_cursor[d.x], 1);
    g_sw[p0] = make_int2(s.x, __float_as_int(w.x));
    int p1 = atomicAdd(&g_cursor[d.y], 1);
    g_sw[p1] = make_int2(s.y, __float_as_int(w.y));
    int p2 = atomicAdd(&g_cursor[d.z], 1);
    g_sw[p2] = make_int2(s.z, __float_as_int(w.z));
    int p3 = atomicAdd(&g_cursor[d.w], 1);
    g_sw[p3] = make_int2(s.w, __float_as_int(w.w));
}

// ---------------------------------------------------------------------------
// Pull: HALF-warp per dst node (16 lanes x 16B = 256B row), 4 edges in flight.
// fp16 gather, fp32 accumulate, bias fused. No atomics.
// ---------------------------------------------------------------------------
__global__ __launch_bounds__(256) void pull_kernel(const float* __restrict__ b,
                                                   float* __restrict__ out) {
    const int n   = (blockIdx.x * blockDim.x + threadIdx.x) >> 4;   // halfwarp id
    const int l16 = threadIdx.x & 15;
    if (n >= N_NODES) return;

    const int start = __ldg(&g_offsets[n]);
    const int end   = __ldg(&g_offsets[n + 1]);

    float acc[8];
#pragma unroll
    for (int i = 0; i < 8; ++i) acc[i] = 0.0f;

    const uint4* sup = (const uint4*)g_supph;   // 8 halves per 16B; 16 uint4 per row

    int j = start;
    for (; j + 3 < end; j += 4) {
        int2 sw0 = __ldg(&g_sw[j]);
        int2 sw1 = __ldg(&g_sw[j + 1]);
        int2 sw2 = __ldg(&g_sw[j + 2]);
        int2 sw3 = __ldg(&g_sw[j + 3]);
        uint4 u0 = __ldg(sup + (size_t)sw0.x * 16 + l16);
        uint4 u1 = __ldg(sup + (size_t)sw1.x * 16 + l16);
        uint4 u2 = __ldg(sup + (size_t)sw2.x * 16 + l16);
        uint4 u3 = __ldg(sup + (size_t)sw3.x * 16 + l16);
        float w0 = __int_as_float(sw0.y), w1 = __int_as_float(sw1.y);
        float w2 = __int_as_float(sw2.y), w3 = __int_as_float(sw3.y);

#pragma unroll
        for (int h = 0; h < 4; ++h) {
            float2 f0 = __half22float2(((const __half2*)&u0)[h]);
            float2 f1 = __half22float2(((const __half2*)&u1)[h]);
            float2 f2 = __half22float2(((const __half2*)&u2)[h]);
            float2 f3 = __half22float2(((const __half2*)&u3)[h]);
            acc[2*h]   = fmaf(w0, f0.x, acc[2*h]);
            acc[2*h+1] = fmaf(w0, f0.y, acc[2*h+1]);
            acc[2*h]   = fmaf(w1, f1.x, acc[2*h]);
            acc[2*h+1] = fmaf(w1, f1.y, acc[2*h+1]);
            acc[2*h]   = fmaf(w2, f2.x, acc[2*h]);
            acc[2*h+1] = fmaf(w2, f2.y, acc[2*h+1]);
            acc[2*h]   = fmaf(w3, f3.x, acc[2*h]);
            acc[2*h+1] = fmaf(w3, f3.y, acc[2*h+1]);
        }
    }
    for (; j < end; ++j) {
        int2 sw0 = __ldg(&g_sw[j]);
        float w0 = __int_as_float(sw0.y);
        uint4 u0 = __ldg(sup + (size_t)sw0.x * 16 + l16);
#pragma unroll
        for (int h = 0; h < 4; ++h) {
            float2 f0 = __half22float2(((const __half2*)&u0)[h]);
            acc[2*h]   = fmaf(w0, f0.x, acc[2*h]);
            acc[2*h+1] = fmaf(w0, f0.y, acc[2*h+1]);
        }
    }

    float4 bv0 = __ldg((const float4*)b + 2 * l16);
    float4 bv1 = __ldg((const float4*)b + 2 * l16 + 1);
    float4 r0 = make_float4(acc[0] + bv0.x, acc[1] + bv0.y, acc[2] + bv0.z, acc[3] + bv0.w);
    float4 r1 = make_float4(acc[4] + bv1.x, acc[5] + bv1.y, acc[6] + bv1.z, acc[7] + bv1.w);
    float4* op = (float4*)out + (size_t)n * (D_OUT / 4) + 2 * l16;
    op[0] = r0;
    op[1] = r1;
}

// ---------------------------------------------------------------------------
// Launch. Inputs: x, edge_src, edge_dst, edge_w, W, b
// GEMM runs on a forked stream, overlapping the CSR build on the main stream.
// kernel_launch is only invoked for the correctness run and the capture call
// (replays execute the graph), so per-call stream/event handles are created
// fresh and intentionally not destroyed (destroying a forked stream mid-
// capture is undefined; leaking ~2 handles total is harmless and allocates
// no tracked device memory).
// ---------------------------------------------------------------------------
extern "C" void kernel_launch(void* const* d_in, const int* in_sizes, int n_in,
                              void* d_out, int out_size) {
    const float* x    = (const float*)d_in[0];
    const int*   esrc = (const int*)d_in[1];
    const int*   edst = (const int*)d_in[2];
    const float* ew   = (const float*)d_in[3];
    const float* W    = (const float*)d_in[4];
    const float* b    = (const float*)d_in[5];
    float* out = (float*)d_out;

    cudaStream_t s1;
    cudaEvent_t ev_fork, ev_join;
    cudaStreamCreateWithFlags(&s1, cudaStreamNonBlocking);
    cudaEventCreateWithFlags(&ev_fork, cudaEventDisableTiming);
    cudaEventCreateWithFlags(&ev_join, cudaEventDisableTiming);

    // fork: GEMM on s1
    cudaEventRecord(ev_fork, 0);
    cudaStreamWaitEvent(s1, ev_fork, 0);
    gemm_tf32_kernel<<<(N_NODES + 127) / 128, 256, 0, s1>>>(x, W);
    cudaEventRecord(ev_join, s1);

    // CSR build on main stream (independent of GEMM)
    hist_kernel<<<(N_EDGES / 4 + 255) / 256, 256>>>(edst);
    scan1_kernel<<<N_SCAN_BLOCKS, SCAN_BLOCK>>>();
    scan2_kernel<<<1, 128>>>();
    scan3_kernel<<<(N_NODES + 255) / 256, 256>>>();
    place_kernel<<<(N_EDGES / 4 + 255) / 256, 256>>>(esrc, edst, ew);

    // join: pull needs both g_supph (s1) and CSR (main)
    cudaStreamWaitEvent(0, ev_join, 0);
    long long pull_threads = (long long)N_NODES * 16;
    pull_kernel<<<(int)((pull_threads + 255) / 256), 256>>>(b, out);
}